// round 4
// baseline (speedup 1.0000x reference)
#include <cuda_runtime.h>
#include <math.h>

#define NC   17
#define MAXB 8
#define FULL 0xffffffffu
#define SMAX 448

struct Params {
  float cw[NC];
  float cz;
  float bg, one_bg;
  float xminxy, invrngxy;
  float zminf, invrngz;
  float dist_thres, act_shift;
  int n_inner, n_outer, S;
  int N, B;
};

__device__ double g_wy[MAXB], g_wynll[MAXB], g_ent[MAXB], g_bi[MAXB], g_w2[MAXB];
__device__ unsigned long long g_pk[MAXB];
__device__ int g_nv[MAXB];

__global__ void nerf_init_kernel() {
  int i = threadIdx.x;
  if (i < MAXB) {
    g_wy[i] = 0.0; g_wynll[i] = 0.0; g_ent[i] = 0.0;
    g_bi[i] = 0.0; g_w2[i] = 0.0;
    g_pk[i] = 0ull; g_nv[i] = 0;
  }
}

__global__ void nerf_final_kernel(float* __restrict__ out, int B) {
  if (threadIdx.x == 0 && blockIdx.x == 0) {
    double ls = 0.0, le = 0.0, ld = 0.0;
    for (int b = 0; b < B; b++) {
      double nv = (double)(g_nv[b] > 1 ? g_nv[b] : 1);
      ls += g_wynll[b] / fmax(g_wy[b], 1e-12);
      le += 0.01 * g_ent[b] / nv;
      double nmax = (double)(g_pk[b] > 0ull ? g_pk[b] : 1ull);
      ld += 0.01 * (g_bi[b] + (1.0 / 3.0) * (1.0 / nmax) * g_w2[b]) / nv;
    }
    double invB = 1.0 / (double)B;
    out[0] = (float)(ls * invB);
    out[1] = (float)(le * invB);
    out[2] = (float)(ld * invB);
  }
}

__global__ void __launch_bounds__(256)
nerf_render_kernel(const float* __restrict__ density,
                   const float* __restrict__ semantic,
                   const float* __restrict__ rays,
                   const float* __restrict__ bda,
                   Params P)
{
  __shared__ float sh_t[SMAX];
  const int S = P.S;
  for (int i = threadIdx.x; i < S; i += blockDim.x) {
    double tv;
    if (i < P.n_inner) {
      tv = (2.0 * (double)i + 1.0) / (double)P.n_inner;
    } else {
      int k = i - P.n_inner;
      double step = (1.0 / 64.0 - 1.0) / (double)P.n_outer;
      double l0 = 1.0 + (double)k * step;
      double l1 = (k + 1 == P.n_outer) ? (1.0 / 64.0) : (1.0 + (double)(k + 1) * step);
      tv = 0.5 * (2.0 / l0 + 2.0 / l1);
    }
    sh_t[i] = (float)tv;
  }
  __syncthreads();

  const int lane = threadIdx.x & 31;
  const int warp = (blockIdx.x * blockDim.x + threadIdx.x) >> 5;
  const int total = P.B * P.N;
  if (warp >= total) return;
  const int b = warp / P.N;

  const float* __restrict__ ray = rays + (size_t)warp * 10;
  const float depth = __ldg(ray + 2);
  // gt_depth = where(depth > 52, 0, depth); valid = gt_depth > 0
  if (!(depth > 0.0f) || (depth > 52.0f)) return;  // invalid ray contributes nothing anywhere
  int gt = (int)__ldg(ray + 3);
  gt = min(max(gt, 0), NC - 1);

  float ox = (__ldg(ray + 4) - 0.0f) / 39.0f;
  float oy = (__ldg(ray + 5) - 0.0f) / 39.0f;
  float oz = (__ldg(ray + 6) - P.cz) / 39.0f;
  float rdx = __ldg(ray + 7), rdy = __ldg(ray + 8), rdz = __ldg(ray + 9);
  float rn = sqrtf(rdx * rdx + rdy * rdy + rdz * rdz);
  rdx /= rn; rdy /= rn; rdz /= rn;

  const float* __restrict__ bm = bda + (size_t)b * 9;
  const float b00 = __ldg(bm + 0), b01 = __ldg(bm + 1), b02 = __ldg(bm + 2);
  const float b10 = __ldg(bm + 3), b11 = __ldg(bm + 4), b12 = __ldg(bm + 5);
  const float b20 = __ldg(bm + 6), b21 = __ldg(bm + 7), b22 = __ldg(bm + 8);
  const float* __restrict__ dvol = density + (size_t)b * 640000;
  const float* __restrict__ svol = semantic + (size_t)b * 640000 * NC;

  float acc[NC];
  #pragma unroll
  for (int c = 0; c < NC; c++) acc[c] = 0.0f;
  float Tcarry = 1.0f, Wc = 0.0f, WMc = 0.0f, cum = 0.0f;
  float prevx = 0.0f, prevy = 0.0f, prevz = 0.0f;
  float bi_acc = 0.0f, w2_acc = 0.0f;
  int pkc = 0;

  const int nch = (S + 31) >> 5;
  for (int ch = 0; ch < nch; ++ch) {
    const int s = (ch << 5) + lane;
    const bool act = s < S;
    const float t = sh_t[act ? s : (S - 1)];

    // point on ray (normalized scene coords)
    float px = ox + rdx * t, py = oy + rdy * t, pz = oz + rdz * t;
    float nrm = sqrtf(px * px + py * py + pz * pz);
    const bool inner = nrm <= 1.0f;
    if (!inner) {
      float invn = 1.0f / nrm;
      float scl = (P.one_bg - P.bg * invn) * invn;
      px *= scl; py *= scl; pz *= scl;
    }
    // bda transform
    const float qx = b00 * px + b01 * py + b02 * pz;
    const float qy = b10 * px + b11 * py + b12 * pz;
    const float qz = b20 * px + b21 * py + b22 * pz;

    // distance to previous (transformed) sample
    float axp = __shfl_up_sync(FULL, qx, 1);
    float ayp = __shfl_up_sync(FULL, qy, 1);
    float azp = __shfl_up_sync(FULL, qz, 1);
    if (lane == 0) { axp = prevx; ayp = prevy; azp = prevz; }
    float ddx = qx - axp, ddy = qy - ayp, ddz = qz - azp;
    float dd = sqrtf(ddx * ddx + ddy * ddy + ddz * ddz);
    if (!act || s == 0) dd = 0.0f;
    prevx = __shfl_sync(FULL, qx, 31);
    prevy = __shfl_sync(FULL, qy, 31);
    prevz = __shfl_sync(FULL, qz, 31);

    // sequential cumulative-distance scan with reset (all lanes replicate state)
    bool myover = false;
    #pragma unroll
    for (int i = 0; i < 32; i++) {
      float di = __shfl_sync(FULL, dd, i);
      int si = (ch << 5) + i;
      if (si >= 1 && si < S) {
        cum += di;
        bool ov = cum > P.dist_thres;
        if (ov) cum = 0.0f;
        if (i == lane) myover = ov;
      }
    }
    const bool keep = act && ((s == 0) ? inner : (inner || myover));

    // grid coords
    float gx = (qx - P.xminxy) * P.invrngxy * 199.0f;
    float gy = (qy - P.xminxy) * P.invrngxy * 199.0f;
    float gz = (qz - P.zminf) * P.invrngz * 15.0f;
    float fxg = floorf(gx), fyg = floorf(gy), fzg = floorf(gz);
    int ix = (int)fxg, iy = (int)fyg, iz = (int)fzg;
    float fx = gx - fxg, fy = gy - fyg, fz = gz - fzg;
    const bool inb = (ix >= -1) && (ix < 200) && (iy >= -1) && (iy < 200) &&
                     (iz >= -1) && (iz < 16);

    float a = 0.0f;
    if (keep) {
      float dens = 0.0f;
      if (inb) {
        #pragma unroll
        for (int dx = 0; dx < 2; dx++) {
          int X = ix + dx;
          if ((unsigned)X < 200u) {
            float wx = dx ? fx : 1.0f - fx;
            #pragma unroll
            for (int dy = 0; dy < 2; dy++) {
              int Y = iy + dy;
              if ((unsigned)Y < 200u) {
                float wxy = wx * (dy ? fy : 1.0f - fy);
                int base = (X * 200 + Y) * 16;
                #pragma unroll
                for (int dz = 0; dz < 2; dz++) {
                  int Z = iz + dz;
                  if ((unsigned)Z < 16u) {
                    dens += wxy * (dz ? fz : 1.0f - fz) * __ldg(dvol + base + Z);
                  }
                }
              }
            }
          }
        }
      }
      // EXACT float32 replication of the reference:
      //   alpha = 1 - (1 + exp(dens+shift))^(-1/2)
      // The f32 add (1 + e) quantizes e onto the 2^-23 grid exactly like
      // jax/numpy float32; __frsqrt_rn gives the correctly-rounded f32 rsqrt.
      float e = expf(dens + P.act_shift);
      float y = 1.0f + e;
      a = 1.0f - __frsqrt_rn(y);
      if (!(a > 1e-7f)) a = 0.0f;
    }

    // exclusive transmittance product via warp scan
    float om = 1.0f - a;
    float sc_ = om;
    #pragma unroll
    for (int d2 = 1; d2 < 32; d2 <<= 1) {
      float v = __shfl_up_sync(FULL, sc_, d2);
      if (lane >= d2) sc_ *= v;
    }
    float upi = __shfl_up_sync(FULL, sc_, 1);
    float Texcl = Tcarry * ((lane == 0) ? 1.0f : upi);
    float wgt = a * Texcl;
    Tcarry *= __shfl_sync(FULL, sc_, 31);

    bool pk = wgt > 1e-7f;
    float w = pk ? wgt : 0.0f;
    pkc += pk ? 1 : 0;

    // distortion loss terms: exclusive cumsums of w and w*m
    float mv = 1.0f - 1.0f / (1.0f + t);
    float wm = w * mv;
    float swv = w, swm = wm;
    #pragma unroll
    for (int d2 = 1; d2 < 32; d2 <<= 1) {
      float v1 = __shfl_up_sync(FULL, swv, d2);
      float v2 = __shfl_up_sync(FULL, swm, d2);
      if (lane >= d2) { swv += v1; swm += v2; }
    }
    float wp = Wc + (swv - w);
    float wmp = WMc + (swm - wm);
    Wc += __shfl_sync(FULL, swv, 31);
    WMc += __shfl_sync(FULL, swm, 31);
    bi_acc += 2.0f * w * (mv * wp - wmp);
    w2_acc += w * w;

    // semantic gather only where it matters
    if (w > 0.0f && inb) {
      #pragma unroll
      for (int dx = 0; dx < 2; dx++) {
        int X = ix + dx;
        if ((unsigned)X < 200u) {
          float wx = (dx ? fx : 1.0f - fx) * w;
          #pragma unroll
          for (int dy = 0; dy < 2; dy++) {
            int Y = iy + dy;
            if ((unsigned)Y < 200u) {
              float wxy = wx * (dy ? fy : 1.0f - fy);
              int base = (X * 200 + Y) * 16;
              #pragma unroll
              for (int dz = 0; dz < 2; dz++) {
                int Z = iz + dz;
                if ((unsigned)Z < 16u) {
                  float cw_ = wxy * (dz ? fz : 1.0f - fz);
                  const float* sp = svol + (size_t)(base + Z) * NC;
                  #pragma unroll
                  for (int c = 0; c < NC; c++)
                    acc[c] = fmaf(cw_, __ldg(sp + c), acc[c]);
                }
              }
            }
          }
        }
      }
    }
  }

  // warp butterfly reductions (all lanes end with full sums)
  #pragma unroll
  for (int d2 = 16; d2 > 0; d2 >>= 1) {
    bi_acc += __shfl_xor_sync(FULL, bi_acc, d2);
    w2_acc += __shfl_xor_sync(FULL, w2_acc, d2);
    pkc    += __shfl_xor_sync(FULL, pkc, d2);
    #pragma unroll
    for (int c = 0; c < NC; c++)
      acc[c] += __shfl_xor_sync(FULL, acc[c], d2);
  }

  if (lane == 0) {
    // entropy of last transmittance
    float p = fminf(fmaxf(Tcarry, 1e-6f), 0.999999f);
    float ent = -(p * logf(p) + (1.0f - p) * logf(1.0f - p));

    // semantic NLL: log_softmax over 17 classes
    float mx = acc[0];
    #pragma unroll
    for (int c = 1; c < NC; c++) mx = fmaxf(mx, acc[c]);
    float se = 0.0f;
    #pragma unroll
    for (int c = 0; c < NC; c++) se += expf(acc[c] - mx);
    // select acc[gt] without forcing acc[] into local memory
    float agt = acc[0];
    #pragma unroll
    for (int c = 1; c < NC; c++) if (c == gt) agt = acc[c];
    float nll = (mx + logf(se)) - agt;
    float wy = P.cw[gt];

    atomicAdd(&g_wy[b],    (double)wy);
    atomicAdd(&g_wynll[b], (double)wy * (double)nll);
    atomicAdd(&g_ent[b],   (double)ent);
    atomicAdd(&g_bi[b],    (double)bi_acc);
    atomicAdd(&g_w2[b],    (double)w2_acc);
    atomicAdd(&g_pk[b],    (unsigned long long)pkc);
    atomicAdd(&g_nv[b],    1);
  }
}

extern "C" void kernel_launch(void* const* d_in, const int* in_sizes, int n_in,
                              void* d_out, int out_size) {
  const float* density  = (const float*)d_in[0];
  const float* semantic = (const float*)d_in[1];
  const float* rays     = (const float*)d_in[2];
  const float* bda      = (const float*)d_in[3];

  int B = in_sizes[3] / 9;
  if (B < 1) B = 1;
  if (B > MAXB) B = MAXB;
  int N = in_sizes[2] / (10 * B);

  Params P;
  // BG_LEN computed exactly as numpy: float32((40-39)/39) then promoted to double
  float bgf = (40.0f - 39.0f) / 39.0f;
  double BG = (double)bgf;
  int n_inner = (int)(2.0 / (2.0 + 2.0 * BG) * 200.0 / 0.5) + 1;
  int n_outer = n_inner / 15;
  P.n_inner = n_inner;
  P.n_outer = n_outer;
  P.S = n_inner + n_outer;
  if (P.S > SMAX) P.S = SMAX;  // safety (expected S = 416)

  P.dist_thres = (float)((2.0 + 2.0 * BG) / 200.0 * 0.5 * 0.95);
  P.act_shift  = (float)log(1.0 / (1.0 - 1e-6) - 1.0);
  P.bg = bgf;
  P.one_bg = (float)(1.0 + BG);

  float xminf = (float)(-1.0 - BG);
  float xmaxf = (float)(1.0 + BG);
  P.xminxy = xminf;
  P.invrngxy = 1.0f / (xmaxf - xminf);

  float rngz32 = 5.4f - (-1.0f);   // float32 arithmetic as in numpy
  float Zf = rngz32 / 80.0f;
  P.zminf = -Zf;
  P.invrngz = 1.0f / (Zf - (-Zf));

  P.cz = (-1.0f + 5.4f) * 0.5f;    // scene center z in float32

  const double freq[NC] = {
    1163161.0, 2309034.0, 188743.0, 2997643.0, 20317180.0, 852476.0,
    243808.0, 2457947.0, 497017.0, 2731022.0, 7224789.0, 214411435.0,
    5565043.0, 63191967.0, 76098082.0, 128860031.0, 141625221.0
  };
  for (int c = 0; c < NC; c++)
    P.cw[c] = (float)(1.0 / log(freq[c] + 0.001));

  P.N = N;
  P.B = B;

  nerf_init_kernel<<<1, 32>>>();

  int totalWarps = B * N;
  long long totalThreads = (long long)totalWarps * 32;
  int blocks = (int)((totalThreads + 255) / 256);
  nerf_render_kernel<<<blocks, 256>>>(density, semantic, rays, bda, P);

  nerf_final_kernel<<<1, 1>>>((float*)d_out, B);
}